// round 12
// baseline (speedup 1.0000x reference)
#include <cuda_runtime.h>
#include <cstdint>

// LSTMModelClassify: B=2048, T=512, D=1, H=50, C=2, 2-layer LSTM + FC.
// R12: G=1 register weights at 15 warps (TPB=480, reg cap 136).
// Warps 0-6: thread tid holds Whh0[tid] (52 regs); warps 7-13: Whh1[tid-224].
// Phase A: both recurrent GEMVs concurrent from registers (h broadcast only).
// Phase B: warps 0-6 stream Wih1 from smem. 3.75 warps/SMSP + reg headroom
// to finally hide LDS latency (R10/R11 ran 2 warps/SMSP at 226+ regs).

#define TPB 480
constexpr int NB    = 14;
constexpr int Hh    = 50;
constexpr int G4    = 200;
constexpr int Tt    = 512;
constexpr int BATCH = 2048;
constexpr int NC    = 2;
constexpr int HS    = 52;    // h row stride (50 + 2 zero pad)
constexpr int PS    = 15;    // plane row stride (odd -> conflict-free)

// shared memory layout (floats)
constexpr int OFF_WI1 = 0;                    // Wih1 [200][52]
constexpr int OFF_XS  = OFF_WI1 + G4 * HS;    // x slice [14][512]
constexpr int OFF_A   = OFF_XS  + NB * Tt;    // h1 [14][52]
constexpr int OFF_B   = OFF_A   + NB * HS;    // h2 [14][52]
constexpr int OFF_P0  = OFF_B   + NB * HS;    // L1 preact (complete, sans x)
constexpr int OFF_P1  = OFF_P0  + G4 * PS;    // Whh1@h2 + bias1
constexpr int OFF_P2  = OFF_P1  + G4 * PS;    // Wih1@h1
constexpr int OFF_WFC = OFF_P2  + G4 * PS;
constexpr int OFF_BFC = OFF_WFC + NC * Hh;
constexpr int SMEMF   = OFF_BFC + NC;         // ~28.1K floats ≈ 112.5KB

__device__ __forceinline__ unsigned long long ffma2(unsigned long long a,
                                                    unsigned long long b,
                                                    unsigned long long c) {
    unsigned long long d;
    asm("fma.rn.f32x2 %0, %1, %2, %3;" : "=l"(d) : "l"(a), "l"(b), "l"(c));
    return d;
}

__device__ __forceinline__ float hadd2(unsigned long long a) {
    unsigned lo, hi;
    asm("mov.b64 {%0, %1}, %2;" : "=r"(lo), "=r"(hi) : "l"(a));
    return __uint_as_float(lo) + __uint_as_float(hi);
}

__device__ __forceinline__ float sigf(float x) {
    float e = __expf(-x);
    return __fdividef(1.0f, 1.0f + e);
}
__device__ __forceinline__ float tanh_(float x) {
    float e = __expf(2.0f * x);
    return 1.0f - __fdividef(2.0f, 1.0f + e);
}

__global__ void __launch_bounds__(TPB, 1) lstm_kernel(
    const float* __restrict__ x,
    const float* __restrict__ Wih0, const float* __restrict__ Whh0,
    const float* __restrict__ bih0, const float* __restrict__ bhh0,
    const float* __restrict__ Wih1, const float* __restrict__ Whh1,
    const float* __restrict__ bih1, const float* __restrict__ bhh1,
    const float* __restrict__ Wfc,  const float* __restrict__ bfc,
    float* __restrict__ out)
{
    extern __shared__ __align__(16) float sm[];
    const int tid = threadIdx.x;
    const int b0  = blockIdx.x * NB;

    for (int i = tid; i < SMEMF; i += TPB) sm[i] = 0.0f;   // zero: pads + h init
    __syncthreads();

    float* WI1  = sm + OFF_WI1;
    float* xs   = sm + OFF_XS;
    float* bufA = sm + OFF_A;
    float* bufB = sm + OFF_B;
    float* P0   = sm + OFF_P0;
    float* P1   = sm + OFF_P1;
    float* P2   = sm + OFF_P2;
    float* wfc  = sm + OFF_WFC;
    float* bfcs = sm + OFF_BFC;

    // stage Wih1 (phase-B streaming), x slice, fc
    for (int i = tid; i < G4 * Hh; i += TPB) {
        int g = i / Hh, k = i % Hh;
        WI1[g * HS + k] = Wih1[i];
    }
    for (int i = tid; i < NB * Tt; i += TPB) {
        int b = i / Tt, t = i % Tt;
        int gb = b0 + b;
        xs[i] = (gb < BATCH) ? x[gb * Tt + t] : 0.0f;
    }
    for (int i = tid; i < NC * Hh; i += TPB) wfc[i] = Wfc[i];
    if (tid < NC) bfcs[tid] = bfc[tid];

    // ---- phase-A roles: warps 0-6 -> Whh0 row tid; warps 7-13 -> Whh1 row tid-224 ----
    const int  warp   = tid >> 5;
    const bool side0  = warp < 7;                // Whh0 side
    const bool side1  = (warp >= 7) && (warp < 14);
    const int  rowRaw = side0 ? tid : (tid - 224);
    const bool gactA  = (side0 || side1) && (rowRaw >= 0) && (rowRaw < G4);
    const int  rowA   = gactA ? rowRaw : 0;

    // G=1 register weights: one 50-float row (26 u64 incl zero pad)
    unsigned long long wreg[26];
    {
        const float* wsrc = side1 ? (Whh1 + rowA * Hh) : (Whh0 + rowA * Hh);
        const unsigned long long* ws = reinterpret_cast<const unsigned long long*>(wsrc);
#pragma unroll
        for (int i = 0; i < 25; ++i) wreg[i] = ws[i];
        wreg[25] = 0ULL;
    }
    float biasA = 0.f, wx = 0.f;
    if (gactA) {
        if (side0) { biasA = bih0[rowA] + bhh0[rowA]; wx = Wih0[rowA]; }
        else       { biasA = bih1[rowA] + bhh1[rowA]; }
    }
    const float* hsrcA = side1 ? bufB : bufA;
    float*       plA   = side1 ? P1   : P0;

    // phase-B role: warps 0-6, row = tid (tid<200)
    const bool gactB = tid < G4;
    const int  rowB  = gactB ? tid : 0;
    const float* wrowB = WI1 + rowB * HS;

    // EW identity: u = tid, tid+480 (u<700)
    int  ewj[2], ewb[2];
    bool ewok[2];
    float c1s[2] = {0.f, 0.f}, c2s[2] = {0.f, 0.f};
#pragma unroll
    for (int r = 0; r < 2; ++r) {
        int u = tid + TPB * r;
        ewok[r] = (u < Hh * NB);
        ewb[r] = u / Hh;
        ewj[r] = u % Hh;
    }

    __syncthreads();

    for (int t = 0; t < Tt; ++t) {
        // ---- Phase A: Whh0@h1(t-1) (warps 0-6) || Whh1@h2(t-1) (warps 7-13)
        //      G=1 register weights; two 7-batch passes (acc = 14 regs) ----
        if (gactA) {
#pragma unroll
            for (int pass = 0; pass < 2; ++pass) {
                const int bb = 7 * pass;
                const float* hsp = hsrcA + bb * HS;
                unsigned long long acc[7];
#pragma unroll
                for (int b = 0; b < 7; ++b) acc[b] = 0ULL;
#pragma unroll
                for (int k4 = 0; k4 < 13; ++k4) {
#pragma unroll
                    for (int b = 0; b < 7; ++b) {
                        ulonglong2 hv = *reinterpret_cast<const ulonglong2*>(hsp + b * HS + 4 * k4);
                        acc[b] = ffma2(hv.x, wreg[2 * k4],     acc[b]);
                        acc[b] = ffma2(hv.y, wreg[2 * k4 + 1], acc[b]);
                    }
                }
                if (side0) {
#pragma unroll
                    for (int b = 0; b < 7; ++b) {
                        float xv = xs[(bb + b) * Tt + t];
                        plA[rowA * PS + bb + b] = hadd2(acc[b]) + fmaf(wx, xv, biasA);
                    }
                } else {
#pragma unroll
                    for (int b = 0; b < 7; ++b)
                        plA[rowA * PS + bb + b] = hadd2(acc[b]) + biasA;
                }
            }
        }
        __syncthreads();

        // ---- L1 elementwise: P0 -> bufA = h1(t) ----
#pragma unroll
        for (int r = 0; r < 2; ++r) if (ewok[r]) {
            int j = ewj[r], b = ewb[r];
            float pi = P0[j * PS + b];
            float pf = P0[(j + 50) * PS + b];
            float pg = P0[(j + 100) * PS + b];
            float po = P0[(j + 150) * PS + b];
            float cc = sigf(pf) * c1s[r] + sigf(pi) * tanh_(pg);
            c1s[r] = cc;
            bufA[b * HS + j] = sigf(po) * tanh_(cc);
        }
        __syncthreads();

        // ---- Phase B (warps 0-6): Wih1 @ h1(t) -> P2, streamed weights ----
        if (gactB) {
            unsigned long long a[NB];
#pragma unroll
            for (int b = 0; b < NB; ++b) a[b] = 0ULL;
#pragma unroll
            for (int k4 = 0; k4 < 13; ++k4) {
                ulonglong2 wv = *reinterpret_cast<const ulonglong2*>(wrowB + 4 * k4);
#pragma unroll
                for (int b = 0; b < NB; ++b) {
                    ulonglong2 hv = *reinterpret_cast<const ulonglong2*>(bufA + b * HS + 4 * k4);
                    a[b] = ffma2(hv.x, wv.x, a[b]);
                    a[b] = ffma2(hv.y, wv.y, a[b]);
                }
            }
#pragma unroll
            for (int b = 0; b < NB; ++b) P2[rowB * PS + b] = hadd2(a[b]);
        }
        __syncthreads();

        // ---- L2 elementwise: P1 + P2 -> bufB = h2(t) ----
#pragma unroll
        for (int r = 0; r < 2; ++r) if (ewok[r]) {
            int j = ewj[r], b = ewb[r];
            float pi = P1[j * PS + b]         + P2[j * PS + b];
            float pf = P1[(j + 50) * PS + b]  + P2[(j + 50) * PS + b];
            float pg = P1[(j + 100) * PS + b] + P2[(j + 100) * PS + b];
            float po = P1[(j + 150) * PS + b] + P2[(j + 150) * PS + b];
            float cc = sigf(pf) * c2s[r] + sigf(pi) * tanh_(pg);
            c2s[r] = cc;
            bufB[b * HS + j] = sigf(po) * tanh_(cc);
        }
        __syncthreads();
    }

    // ---- Final FC on last h2 ----
    if (tid < NB * NC) {
        int bl = tid >> 1;
        int c  = tid & 1;
        int gb = b0 + bl;
        if (gb < BATCH) {
            float sacc = bfcs[c];
#pragma unroll
            for (int j = 0; j < Hh; ++j) sacc += wfc[c * Hh + j] * bufB[bl * HS + j];
            out[gb * NC + c] = sacc;
        }
    }
}

extern "C" void kernel_launch(void* const* d_in, const int* in_sizes, int n_in,
                              void* d_out, int out_size) {
    const float* x    = (const float*)d_in[0];
    const float* Wih0 = (const float*)d_in[1];
    const float* Whh0 = (const float*)d_in[2];
    const float* bih0 = (const float*)d_in[3];
    const float* bhh0 = (const float*)d_in[4];
    const float* Wih1 = (const float*)d_in[5];
    const float* Whh1 = (const float*)d_in[6];
    const float* bih1 = (const float*)d_in[7];
    const float* bhh1 = (const float*)d_in[8];
    const float* Wfc  = (const float*)d_in[9];
    const float* bfc  = (const float*)d_in[10];
    float* out = (float*)d_out;

    const int smem_bytes = SMEMF * (int)sizeof(float);
    cudaFuncSetAttribute(lstm_kernel, cudaFuncAttributeMaxDynamicSharedMemorySize, smem_bytes);

    const int grid = (BATCH + NB - 1) / NB;   // 147 blocks, one wave
    lstm_kernel<<<grid, TPB, smem_bytes>>>(x, Wih0, Whh0, bih0, bhh0,
                                           Wih1, Whh1, bih1, bhh1,
                                           Wfc, bfc, out);
}

// round 13
// speedup vs baseline: 1.1868x; 1.1868x over previous
#include <cuda_runtime.h>
#include <cstdint>

// LSTMModelClassify: B=2048, T=512, D=1, H=50, C=2, 2-layer LSTM + FC.
// R13: 2 blocks/SM. NB=7, TPB=224, __launch_bounds__(224,2), grid=293.
// 14 warps/SM (3.5/SMSP); cross-block overlap absorbs barrier stalls.
// Phase A hybrid G=2: row p in registers, row p+100 streamed from smem
// (rows 100-199 of Whh0/Whh1 staged). Phase B: Wih1 streamed, G=1.
// x read via broadcast LDG (no smem stage) to fit 2 blocks in smem.

#define TPB 224
constexpr int NB    = 7;
constexpr int Hh    = 50;
constexpr int G4    = 200;
constexpr int Tt    = 512;
constexpr int BATCH = 2048;
constexpr int NC    = 2;
constexpr int HS    = 52;    // weight/h row stride (50 + 2 zero pad)
constexpr int PS    = 9;     // plane row stride (9 coprime 32 -> conflict-free)

// shared memory layout (floats)
constexpr int OFF_WI1 = 0;                     // Wih1 [200][52]
constexpr int OFF_WH0 = OFF_WI1 + G4 * HS;     // Whh0 rows 100-199 [100][52]
constexpr int OFF_WH1 = OFF_WH0 + 100 * HS;    // Whh1 rows 100-199 [100][52]
constexpr int OFF_A   = OFF_WH1 + 100 * HS;    // h1 [7][52]
constexpr int OFF_B   = OFF_A   + NB * HS;     // h2 [7][52]
constexpr int OFF_P0  = OFF_B   + NB * HS;     // L1 preact
constexpr int OFF_P1  = OFF_P0  + G4 * PS;     // Whh1@h2 + bias1
constexpr int OFF_P2  = OFF_P1  + G4 * PS;     // Wih1@h1
constexpr int OFF_WFC = OFF_P2  + G4 * PS;
constexpr int OFF_BFC = OFF_WFC + NC * Hh;
constexpr int SMEMF   = OFF_BFC + NC;          // 27030 floats = 108120 B

__device__ __forceinline__ unsigned long long ffma2(unsigned long long a,
                                                    unsigned long long b,
                                                    unsigned long long c) {
    unsigned long long d;
    asm("fma.rn.f32x2 %0, %1, %2, %3;" : "=l"(d) : "l"(a), "l"(b), "l"(c));
    return d;
}

__device__ __forceinline__ float hadd2(unsigned long long a) {
    unsigned lo, hi;
    asm("mov.b64 {%0, %1}, %2;" : "=r"(lo), "=r"(hi) : "l"(a));
    return __uint_as_float(lo) + __uint_as_float(hi);
}

__device__ __forceinline__ float sigf(float x) {
    float e = __expf(-x);
    return __fdividef(1.0f, 1.0f + e);
}
__device__ __forceinline__ float tanh_(float x) {
    float e = __expf(2.0f * x);
    return 1.0f - __fdividef(2.0f, 1.0f + e);
}

__global__ void __launch_bounds__(TPB, 2) lstm_kernel(
    const float* __restrict__ x,
    const float* __restrict__ Wih0, const float* __restrict__ Whh0,
    const float* __restrict__ bih0, const float* __restrict__ bhh0,
    const float* __restrict__ Wih1, const float* __restrict__ Whh1,
    const float* __restrict__ bih1, const float* __restrict__ bhh1,
    const float* __restrict__ Wfc,  const float* __restrict__ bfc,
    float* __restrict__ out)
{
    extern __shared__ __align__(16) float sm[];
    const int tid = threadIdx.x;
    const int b0  = blockIdx.x * NB;

    for (int i = tid; i < SMEMF; i += TPB) sm[i] = 0.0f;   // zero: pads + h init
    __syncthreads();

    float* WI1  = sm + OFF_WI1;
    float* WH0  = sm + OFF_WH0;
    float* WH1  = sm + OFF_WH1;
    float* bufA = sm + OFF_A;
    float* bufB = sm + OFF_B;
    float* P0   = sm + OFF_P0;
    float* P1   = sm + OFF_P1;
    float* P2   = sm + OFF_P2;
    float* wfc  = sm + OFF_WFC;
    float* bfcs = sm + OFF_BFC;

    // stage Wih1 (full) and Whh0/Whh1 rows 100-199
    for (int i = tid; i < G4 * Hh; i += TPB) {
        int g = i / Hh, k = i % Hh;
        WI1[g * HS + k] = Wih1[i];
    }
    for (int i = tid; i < 100 * Hh; i += TPB) {
        int g = i / Hh, k = i % Hh;
        WH0[g * HS + k] = Whh0[(g + 100) * Hh + k];
        WH1[g * HS + k] = Whh1[(g + 100) * Hh + k];
    }
    for (int i = tid; i < NC * Hh; i += TPB) wfc[i] = Wfc[i];
    if (tid < NC) bfcs[tid] = bfc[tid];

    // ---- phase-A roles: tid<100 -> Whh0 rows (tid, tid+100);
    //      100<=tid<200 -> Whh1 rows (tid-100, tid). tid>=200: clamped dummy. ----
    const bool side1 = tid >= 100;
    const int  p     = side1 ? (tid < 200 ? tid - 100 : 99) : tid;   // 0..99
    const bool gactA = tid < 200;

    // register weights: row p of the recurrent matrix (26 u64 incl zero pad)
    unsigned long long wreg[26];
    {
        const float* wsrc = side1 ? (Whh1 + p * Hh) : (Whh0 + p * Hh);
        const unsigned long long* ws = reinterpret_cast<const unsigned long long*>(wsrc);
#pragma unroll
        for (int i = 0; i < 25; ++i) wreg[i] = ws[i];
        wreg[25] = 0ULL;
    }
    // smem-streamed row: p+100 of same matrix
    const float* wsRow = (side1 ? WH1 : WH0) + p * HS;

    float bA0, bA1, wx0 = 0.f, wx1 = 0.f;
    if (!side1) {
        bA0 = bih0[p] + bhh0[p];
        bA1 = bih0[p + 100] + bhh0[p + 100];
        wx0 = Wih0[p];
        wx1 = Wih0[p + 100];
    } else {
        bA0 = bih1[p] + bhh1[p];
        bA1 = bih1[p + 100] + bhh1[p + 100];
    }
    const float* hsrcA = side1 ? bufB : bufA;
    float*       plA   = side1 ? P1   : P0;

    // x offsets (broadcast LDG per step; clamped for the partial last block)
    int xoff[NB];
#pragma unroll
    for (int b = 0; b < NB; ++b) {
        int gb = b0 + b;
        xoff[b] = (gb < BATCH ? gb : BATCH - 1) * Tt;
    }

    // phase-B role: row = tid (tid<200), streamed Wih1
    const bool gactB = tid < G4;
    const int  rowB  = gactB ? tid : 0;
    const float* wrowB = WI1 + rowB * HS;

    // EW identity: u = tid, tid+224 (u<350)
    int  ewj[2], ewb[2];
    bool ewok[2];
    float c1s[2] = {0.f, 0.f}, c2s[2] = {0.f, 0.f};
#pragma unroll
    for (int r = 0; r < 2; ++r) {
        int u = tid + TPB * r;
        ewok[r] = (u < Hh * NB);
        ewb[r] = u / Hh;
        ewj[r] = u % Hh;
    }

    __syncthreads();

    for (int t = 0; t < Tt; ++t) {
        // ---- Phase A: hybrid G=2 — row p from regs, row p+100 from smem ----
        {
            unsigned long long a0[NB], a1[NB];
#pragma unroll
            for (int b = 0; b < NB; ++b) { a0[b] = 0ULL; a1[b] = 0ULL; }
#pragma unroll
            for (int k4 = 0; k4 < 13; ++k4) {
                ulonglong2 wv = *reinterpret_cast<const ulonglong2*>(wsRow + 4 * k4);
#pragma unroll
                for (int b = 0; b < NB; ++b) {
                    ulonglong2 hv = *reinterpret_cast<const ulonglong2*>(hsrcA + b * HS + 4 * k4);
                    a0[b] = ffma2(hv.x, wreg[2 * k4],     a0[b]);
                    a0[b] = ffma2(hv.y, wreg[2 * k4 + 1], a0[b]);
                    a1[b] = ffma2(hv.x, wv.x, a1[b]);
                    a1[b] = ffma2(hv.y, wv.y, a1[b]);
                }
            }
            if (gactA) {
                if (!side1) {
#pragma unroll
                    for (int b = 0; b < NB; ++b) {
                        float xv = __ldg(x + xoff[b] + t);
                        plA[p * PS + b]         = hadd2(a0[b]) + fmaf(wx0, xv, bA0);
                        plA[(p + 100) * PS + b] = hadd2(a1[b]) + fmaf(wx1, xv, bA1);
                    }
                } else {
#pragma unroll
                    for (int b = 0; b < NB; ++b) {
                        plA[p * PS + b]         = hadd2(a0[b]) + bA0;
                        plA[(p + 100) * PS + b] = hadd2(a1[b]) + bA1;
                    }
                }
            }
        }
        __syncthreads();

        // ---- L1 elementwise: P0 -> bufA = h1(t) ----
#pragma unroll
        for (int r = 0; r < 2; ++r) if (ewok[r]) {
            int j = ewj[r], b = ewb[r];
            float pi = P0[j * PS + b];
            float pf = P0[(j + 50) * PS + b];
            float pg = P0[(j + 100) * PS + b];
            float po = P0[(j + 150) * PS + b];
            float cc = sigf(pf) * c1s[r] + sigf(pi) * tanh_(pg);
            c1s[r] = cc;
            bufA[b * HS + j] = sigf(po) * tanh_(cc);
        }
        __syncthreads();

        // ---- Phase B: Wih1 @ h1(t) -> P2 (rows = tid, streamed weights) ----
        {
            unsigned long long a[NB];
#pragma unroll
            for (int b = 0; b < NB; ++b) a[b] = 0ULL;
#pragma unroll
            for (int k4 = 0; k4 < 13; ++k4) {
                ulonglong2 wv = *reinterpret_cast<const ulonglong2*>(wrowB + 4 * k4);
#pragma unroll
                for (int b = 0; b < NB; ++b) {
                    ulonglong2 hv = *reinterpret_cast<const ulonglong2*>(bufA + b * HS + 4 * k4);
                    a[b] = ffma2(hv.x, wv.x, a[b]);
                    a[b] = ffma2(hv.y, wv.y, a[b]);
                }
            }
            if (gactB) {
#pragma unroll
                for (int b = 0; b < NB; ++b) P2[rowB * PS + b] = hadd2(a[b]);
            }
        }
        __syncthreads();

        // ---- L2 elementwise: P1 + P2 -> bufB = h2(t) ----
#pragma unroll
        for (int r = 0; r < 2; ++r) if (ewok[r]) {
            int j = ewj[r], b = ewb[r];
            float pi = P1[j * PS + b]         + P2[j * PS + b];
            float pf = P1[(j + 50) * PS + b]  + P2[(j + 50) * PS + b];
            float pg = P1[(j + 100) * PS + b] + P2[(j + 100) * PS + b];
            float po = P1[(j + 150) * PS + b] + P2[(j + 150) * PS + b];
            float cc = sigf(pf) * c2s[r] + sigf(pi) * tanh_(pg);
            c2s[r] = cc;
            bufB[b * HS + j] = sigf(po) * tanh_(cc);
        }
        __syncthreads();
    }

    // ---- Final FC on last h2 ----
    if (tid < NB * NC) {
        int bl = tid >> 1;
        int c  = tid & 1;
        int gb = b0 + bl;
        if (gb < BATCH) {
            float sacc = bfcs[c];
#pragma unroll
            for (int j = 0; j < Hh; ++j) sacc += wfc[c * Hh + j] * bufB[bl * HS + j];
            out[gb * NC + c] = sacc;
        }
    }
}

extern "C" void kernel_launch(void* const* d_in, const int* in_sizes, int n_in,
                              void* d_out, int out_size) {
    const float* x    = (const float*)d_in[0];
    const float* Wih0 = (const float*)d_in[1];
    const float* Whh0 = (const float*)d_in[2];
    const float* bih0 = (const float*)d_in[3];
    const float* bhh0 = (const float*)d_in[4];
    const float* Wih1 = (const float*)d_in[5];
    const float* Whh1 = (const float*)d_in[6];
    const float* bih1 = (const float*)d_in[7];
    const float* bhh1 = (const float*)d_in[8];
    const float* Wfc  = (const float*)d_in[9];
    const float* bfc  = (const float*)d_in[10];
    float* out = (float*)d_out;

    const int smem_bytes = SMEMF * (int)sizeof(float);
    cudaFuncSetAttribute(lstm_kernel, cudaFuncAttributeMaxDynamicSharedMemorySize, smem_bytes);

    const int grid = (BATCH + NB - 1) / NB;   // 293 blocks, 2 per SM, one wave
    lstm_kernel<<<grid, TPB, smem_bytes>>>(x, Wih0, Whh0, bih0, bhh0,
                                           Wih1, Whh1, bih1, bhh1,
                                           Wfc, bfc, out);
}